// round 10
// baseline (speedup 1.0000x reference)
#include <cuda_runtime.h>
#include <math.h>

// ---------------- problem constants ----------------
#define CDIM 768
#define LNUM 6
#define HNUM 12
#define HD   64
#define TLEN 1024
#define BSZ  2
#define VDIM 50257
#define VPAD 50304               // 393 * 128, zero-padded
#define MROWS (BSZ * TLEN)       // 2048

// ---------------- scratch (no allocation allowed) ----------------
__device__ __align__(16) float g_x   [MROWS * CDIM];
__device__ __align__(16) float g_xn  [MROWS * CDIM];
__device__ __align__(16) float g_att [MROWS * CDIM];
__device__ __align__(16) float g_qkv [MROWS * 3 * CDIM];
__device__ __align__(16) float g_h   [MROWS * 4 * CDIM];
__device__ __align__(16) float g_embT[CDIM * VPAD];

// ---------------- embedding ----------------
__global__ void embed_kernel(const int* __restrict__ idx,
                             const float* __restrict__ emb,
                             const float* __restrict__ pos) {
    int n = blockIdx.x;
    int tok = idx[n];
    int t = n & (TLEN - 1);
    const float* e = emb + (size_t)tok * CDIM;
    const float* p = pos + (size_t)t * CDIM;
    float* xr = g_x + (size_t)n * CDIM;
    for (int c = threadIdx.x; c < CDIM; c += blockDim.x)
        xr[c] = e[c] + p[c];
}

// ---------------- transpose emb [V,C] -> embT [C, VPAD] (zero padded) ----------------
__global__ void transpose_kernel(const float* __restrict__ emb) {
    __shared__ float tile[32][33];
    int v0 = blockIdx.x * 32;
    int c0 = blockIdx.y * 32;
    for (int i = threadIdx.y; i < 32; i += 8) {
        int v = v0 + i;
        tile[i][threadIdx.x] = (v < VDIM) ? emb[(size_t)v * CDIM + c0 + threadIdx.x] : 0.f;
    }
    __syncthreads();
    for (int i = threadIdx.y; i < 32; i += 8) {
        g_embT[(size_t)(c0 + i) * VPAD + v0 + threadIdx.x] = tile[threadIdx.x][i];
    }
}

// ---------------- layernorm (one block per row, C=768) ----------------
__global__ void __launch_bounds__(256) ln_kernel(const float* __restrict__ x,
                                                 const float* __restrict__ w,
                                                 const float* __restrict__ bb,
                                                 float* __restrict__ y) {
    __shared__ float red[8];
    __shared__ float bc[2];
    int row = blockIdx.x, t = threadIdx.x;
    const float* xr = x + (size_t)row * CDIM;
    float v0 = xr[t], v1 = xr[t + 256], v2 = xr[t + 512];
    float s = v0 + v1 + v2;
    #pragma unroll
    for (int o = 16; o; o >>= 1) s += __shfl_xor_sync(0xffffffffu, s, o);
    if ((t & 31) == 0) red[t >> 5] = s;
    __syncthreads();
    if (t == 0) {
        float tt = 0.f;
        #pragma unroll
        for (int i = 0; i < 8; i++) tt += red[i];
        bc[0] = tt * (1.f / 768.f);
    }
    __syncthreads();
    float mu = bc[0];
    float d0 = v0 - mu, d1 = v1 - mu, d2 = v2 - mu;
    float q = d0 * d0 + d1 * d1 + d2 * d2;
    __syncthreads();   // red reuse
    #pragma unroll
    for (int o = 16; o; o >>= 1) q += __shfl_xor_sync(0xffffffffu, q, o);
    if ((t & 31) == 0) red[t >> 5] = q;
    __syncthreads();
    if (t == 0) {
        float tt = 0.f;
        #pragma unroll
        for (int i = 0; i < 8; i++) tt += red[i];
        bc[1] = rsqrtf(tt * (1.f / 768.f) + 1e-5f);
    }
    __syncthreads();
    float inv = bc[1];
    float* yr = y + (size_t)row * CDIM;
    yr[t]       = d0 * inv * w[t]       + bb[t];
    yr[t + 256] = d1 * inv * w[t + 256] + bb[t + 256];
    yr[t + 512] = d2 * inv * w[t + 512] + bb[t + 512];
}

// ---------------- SGEMM: C[M,N] = A[M,K] @ B[K,N]  (lda = K) ----------------
// EPI: 0 = none, 1 = +bias then GELU, 2 = +resid, 3 = +bias +resid
#define GBM 128
#define GBN 128
#define GBK 16

template<int EPI>
__global__ void __launch_bounds__(256) gemm_kernel(
    const float* __restrict__ A, const float* __restrict__ B, float* __restrict__ Cc,
    const float* __restrict__ bias, const float* __restrict__ resid,
    int N, int K, int ldb, int ldc)
{
    __shared__ float As[GBK][132];   // K-transposed A tile, padded stride
    __shared__ float Bs[GBK][GBN];

    int tid = threadIdx.x;
    int bn = blockIdx.x * GBN;
    int bm = blockIdx.y * GBM;
    int tx = tid & 15, ty = tid >> 4;

    int arow = tid >> 2;             // 0..63
    int acol = (tid & 3) << 2;       // 0,4,8,12
    int brow = tid >> 5;             // 0..7
    int bcol = (tid & 31) << 2;      // 0..124

    const float* Ap = A + (size_t)(bm + arow) * K + acol;
    const float* Bp = B + (size_t)brow * ldb + bn + bcol;

    float4 ra0 = *(const float4*)Ap;
    float4 ra1 = *(const float4*)(Ap + (size_t)64 * K);
    float4 rb0 = *(const float4*)Bp;
    float4 rb1 = *(const float4*)(Bp + (size_t)8 * ldb);

    float acc[8][8];
    #pragma unroll
    for (int i = 0; i < 8; i++)
        #pragma unroll
        for (int j = 0; j < 8; j++) acc[i][j] = 0.f;

    int nk = K / GBK;
    for (int kt = 0; kt < nk; kt++) {
        As[acol + 0][arow] = ra0.x; As[acol + 1][arow] = ra0.y;
        As[acol + 2][arow] = ra0.z; As[acol + 3][arow] = ra0.w;
        As[acol + 0][arow + 64] = ra1.x; As[acol + 1][arow + 64] = ra1.y;
        As[acol + 2][arow + 64] = ra1.z; As[acol + 3][arow + 64] = ra1.w;
        *(float4*)&Bs[brow][bcol]     = rb0;
        *(float4*)&Bs[brow + 8][bcol] = rb1;
        __syncthreads();

        if (kt + 1 < nk) {
            ra0 = *(const float4*)(Ap + (kt + 1) * GBK);
            ra1 = *(const float4*)(Ap + (size_t)64 * K + (kt + 1) * GBK);
            rb0 = *(const float4*)(Bp + (size_t)(kt + 1) * GBK * ldb);
            rb1 = *(const float4*)(Bp + (size_t)((kt + 1) * GBK + 8) * ldb);
        }

        #pragma unroll
        for (int k = 0; k < GBK; k++) {
            float4 a0 = *(const float4*)&As[k][ty * 8];
            float4 a1 = *(const float4*)&As[k][ty * 8 + 4];
            float4 b0 = *(const float4*)&Bs[k][tx * 8];
            float4 b1 = *(const float4*)&Bs[k][tx * 8 + 4];
            float av[8] = {a0.x, a0.y, a0.z, a0.w, a1.x, a1.y, a1.z, a1.w};
            float bv[8] = {b0.x, b0.y, b0.z, b0.w, b1.x, b1.y, b1.z, b1.w};
            #pragma unroll
            for (int i = 0; i < 8; i++)
                #pragma unroll
                for (int j = 0; j < 8; j++)
                    acc[i][j] = fmaf(av[i], bv[j], acc[i][j]);
        }
        __syncthreads();
    }

    float bvv[8];
    if (EPI == 1 || EPI == 3) {
        #pragma unroll
        for (int j = 0; j < 8; j++) {
            int n = bn + tx * 8 + j;
            bvv[j] = (n < N) ? bias[n] : 0.f;
        }
    }
    #pragma unroll
    for (int i = 0; i < 8; i++) {
        int mrow = bm + ty * 8 + i;
        float* crow = Cc + (size_t)mrow * ldc;
        const float* rrow = (EPI == 2 || EPI == 3) ? (resid + (size_t)mrow * ldc) : nullptr;
        #pragma unroll
        for (int j = 0; j < 8; j++) {
            int n = bn + tx * 8 + j;
            if (n >= N) continue;
            float v = acc[i][j];
            if (EPI == 1 || EPI == 3) v += bvv[j];
            if (EPI == 1) v = 0.5f * v * (1.f + erff(v * 0.70710678118654752f));
            if (EPI == 2 || EPI == 3) v += rrow[n];
            crow[n] = v;
        }
    }
}

// ---------------- fused causal flash attention ----------------
// Block = (q-tile of 64 rows, head h, batch b). 128 threads:
// ty = tid/8 in [0,16) -> 4 q-rows each; tx = tid%8 -> 8 cols each.
#define FA_SM_FLOATS (3 * 64 * 65 + 64 * 64)
#define FA_SM_BYTES  (FA_SM_FLOATS * 4)

__global__ void __launch_bounds__(128) flash_kernel(const float* __restrict__ qkv,
                                                    float* __restrict__ out) {
    extern __shared__ float sm[];
    float* Qt = sm;                  // [64 d][65] Q transposed, pre-scaled
    float* Kt = Qt + 64 * 65;        // [64 d][65] K transposed
    float* Ps = Kt + 64 * 65;        // [64 r][65] probabilities
    float* Vs = Ps + 64 * 65;        // [64 r][64 d]

    const int C3 = 3 * CDIM;
    int qt = blockIdx.x, h = blockIdx.y, b = blockIdx.z;
    int tid = threadIdx.x;
    int tx = tid & 7, ty = tid >> 3;

    const float* base = qkv + (size_t)b * TLEN * C3 + h * HD;

    // load Q tile (transposed, scaled by 1/sqrt(64))
    for (int i = tid; i < 64 * 16; i += 128) {
        int r = i >> 4;
        int d4 = (i & 15) * 4;
        float4 qv = *(const float4*)(base + (size_t)(qt * 64 + r) * C3 + d4);
        Qt[(d4 + 0) * 65 + r] = qv.x * 0.125f;
        Qt[(d4 + 1) * 65 + r] = qv.y * 0.125f;
        Qt[(d4 + 2) * 65 + r] = qv.z * 0.125f;
        Qt[(d4 + 3) * 65 + r] = qv.w * 0.125f;
    }

    float o[4][8];
    float m[4], lsum[4];
    #pragma unroll
    for (int i = 0; i < 4; i++) {
        m[i] = -1e30f; lsum[i] = 0.f;
        #pragma unroll
        for (int j = 0; j < 8; j++) o[i][j] = 0.f;
    }

    for (int kt = 0; kt <= qt; kt++) {
        __syncthreads();   // protect Kt/Vs/Ps from previous iteration
        for (int i = tid; i < 64 * 16; i += 128) {
            int r = i >> 4;
            int d4 = (i & 15) * 4;
            const float* krow = base + CDIM + (size_t)(kt * 64 + r) * C3;
            float4 kv = *(const float4*)(krow + d4);
            Kt[(d4 + 0) * 65 + r] = kv.x;
            Kt[(d4 + 1) * 65 + r] = kv.y;
            Kt[(d4 + 2) * 65 + r] = kv.z;
            Kt[(d4 + 3) * 65 + r] = kv.w;
            float4 vv = *(const float4*)(krow + CDIM + d4);
            *(float4*)(Vs + r * 64 + d4) = vv;
        }
        __syncthreads();

        // S = Q @ K^T (64x64, 4x8 per thread)
        float s[4][8];
        #pragma unroll
        for (int i = 0; i < 4; i++)
            #pragma unroll
            for (int j = 0; j < 8; j++) s[i][j] = 0.f;

        #pragma unroll 8
        for (int k = 0; k < 64; k++) {
            float qa[4], kb[8];
            #pragma unroll
            for (int i = 0; i < 4; i++) qa[i] = Qt[k * 65 + ty * 4 + i];
            #pragma unroll
            for (int j = 0; j < 8; j++) kb[j] = Kt[k * 65 + tx * 8 + j];
            #pragma unroll
            for (int i = 0; i < 4; i++)
                #pragma unroll
                for (int j = 0; j < 8; j++)
                    s[i][j] = fmaf(qa[i], kb[j], s[i][j]);
        }

        if (kt == qt) {  // causal mask on diagonal tile
            #pragma unroll
            for (int i = 0; i < 4; i++)
                #pragma unroll
                for (int j = 0; j < 8; j++)
                    if (tx * 8 + j > ty * 4 + i) s[i][j] = -1e30f;
        }

        // online softmax + write P to smem
        #pragma unroll
        for (int i = 0; i < 4; i++) {
            float mt = s[i][0];
            #pragma unroll
            for (int j = 1; j < 8; j++) mt = fmaxf(mt, s[i][j]);
            mt = fmaxf(mt, __shfl_xor_sync(0xffffffffu, mt, 1));
            mt = fmaxf(mt, __shfl_xor_sync(0xffffffffu, mt, 2));
            mt = fmaxf(mt, __shfl_xor_sync(0xffffffffu, mt, 4));
            float mn = fmaxf(m[i], mt);
            float alpha = __expf(m[i] - mn);
            m[i] = mn;
            float rs = 0.f;
            #pragma unroll
            for (int j = 0; j < 8; j++) {
                float p = __expf(s[i][j] - mn);
                s[i][j] = p;
                rs += p;
            }
            rs += __shfl_xor_sync(0xffffffffu, rs, 1);
            rs += __shfl_xor_sync(0xffffffffu, rs, 2);
            rs += __shfl_xor_sync(0xffffffffu, rs, 4);
            lsum[i] = lsum[i] * alpha + rs;
            #pragma unroll
            for (int j = 0; j < 8; j++) o[i][j] *= alpha;
            #pragma unroll
            for (int j = 0; j < 8; j++)
                Ps[(ty * 4 + i) * 65 + tx * 8 + j] = s[i][j];
        }
        __syncthreads();

        // O += P @ V
        #pragma unroll 4
        for (int kk = 0; kk < 64; kk++) {
            float pa[4];
            #pragma unroll
            for (int i = 0; i < 4; i++) pa[i] = Ps[(ty * 4 + i) * 65 + kk];
            float4 v0 = *(const float4*)(Vs + kk * 64 + tx * 8);
            float4 v1 = *(const float4*)(Vs + kk * 64 + tx * 8 + 4);
            #pragma unroll
            for (int i = 0; i < 4; i++) {
                o[i][0] = fmaf(pa[i], v0.x, o[i][0]);
                o[i][1] = fmaf(pa[i], v0.y, o[i][1]);
                o[i][2] = fmaf(pa[i], v0.z, o[i][2]);
                o[i][3] = fmaf(pa[i], v0.w, o[i][3]);
                o[i][4] = fmaf(pa[i], v1.x, o[i][4]);
                o[i][5] = fmaf(pa[i], v1.y, o[i][5]);
                o[i][6] = fmaf(pa[i], v1.z, o[i][6]);
                o[i][7] = fmaf(pa[i], v1.w, o[i][7]);
            }
        }
    }

    // write out[(b,t), h*64 + d]
    #pragma unroll
    for (int i = 0; i < 4; i++) {
        float inv = 1.f / lsum[i];
        int r = qt * 64 + ty * 4 + i;
        float* orow = out + ((size_t)(b * TLEN + r)) * CDIM + h * HD + tx * 8;
        float4 w0 = make_float4(o[i][0] * inv, o[i][1] * inv, o[i][2] * inv, o[i][3] * inv);
        float4 w1 = make_float4(o[i][4] * inv, o[i][5] * inv, o[i][6] * inv, o[i][7] * inv);
        *(float4*)(orow)     = w0;
        *(float4*)(orow + 4) = w1;
    }
}

// ---------------- launch ----------------
extern "C" void kernel_launch(void* const* d_in, const int* in_sizes, int n_in,
                              void* d_out, int out_size) {
    (void)in_sizes; (void)n_in; (void)out_size;
    const int*   idx   = (const int*)d_in[0];
    const float* emb   = (const float*)d_in[1];
    const float* pos   = (const float*)d_in[2];
    const float* Wqkv  = (const float*)d_in[3];
    const float* Wproj = (const float*)d_in[4];
    const float* ln1w  = (const float*)d_in[5];
    const float* ln1b  = (const float*)d_in[6];
    const float* ln2w  = (const float*)d_in[7];
    const float* ln2b  = (const float*)d_in[8];
    const float* W1    = (const float*)d_in[9];
    const float* b1    = (const float*)d_in[10];
    const float* W2    = (const float*)d_in[11];
    const float* b2    = (const float*)d_in[12];
    const float* lnfw  = (const float*)d_in[13];
    const float* lnfb  = (const float*)d_in[14];
    float* out = (float*)d_out;

    float *x, *xn, *att, *qkv, *hbuf, *embT;
    cudaGetSymbolAddress((void**)&x,    g_x);
    cudaGetSymbolAddress((void**)&xn,   g_xn);
    cudaGetSymbolAddress((void**)&att,  g_att);
    cudaGetSymbolAddress((void**)&qkv,  g_qkv);
    cudaGetSymbolAddress((void**)&hbuf, g_h);
    cudaGetSymbolAddress((void**)&embT, g_embT);

    cudaFuncSetAttribute(flash_kernel, cudaFuncAttributeMaxDynamicSharedMemorySize, FA_SM_BYTES);

    transpose_kernel<<<dim3(VPAD / 32, CDIM / 32), dim3(32, 8)>>>(emb);
    embed_kernel<<<MROWS, 256>>>(idx, emb, pos);

    const dim3 blk(256);
    for (int l = 0; l < LNUM; l++) {
        ln_kernel<<<MROWS, blk>>>(x, ln1w + l * CDIM, ln1b + l * CDIM, xn);

        gemm_kernel<0><<<dim3(3 * CDIM / GBN, MROWS / GBM), blk>>>(
            xn, Wqkv + (size_t)l * CDIM * 3 * CDIM, qkv,
            nullptr, nullptr, 3 * CDIM, CDIM, 3 * CDIM, 3 * CDIM);

        flash_kernel<<<dim3(TLEN / 64, HNUM, BSZ), 128, FA_SM_BYTES>>>(qkv, att);

        gemm_kernel<2><<<dim3(CDIM / GBN, MROWS / GBM), blk>>>(
            att, Wproj + (size_t)l * CDIM * CDIM, x,
            nullptr, x, CDIM, CDIM, CDIM, CDIM);

        ln_kernel<<<MROWS, blk>>>(x, ln2w + l * CDIM, ln2b + l * CDIM, xn);

        gemm_kernel<1><<<dim3(4 * CDIM / GBN, MROWS / GBM), blk>>>(
            xn, W1 + (size_t)l * CDIM * 4 * CDIM, hbuf,
            b1 + (size_t)l * 4 * CDIM, nullptr, 4 * CDIM, CDIM, 4 * CDIM, 4 * CDIM);

        gemm_kernel<3><<<dim3(CDIM / GBN, MROWS / GBM), blk>>>(
            hbuf, W2 + (size_t)l * 4 * CDIM * CDIM, x,
            b2 + (size_t)l * CDIM, x, CDIM, 4 * CDIM, CDIM, CDIM);
    }

    ln_kernel<<<MROWS, blk>>>(x, lnfw, lnfb, xn);

    // tied head: xn [2048,768] @ embT [768, VPAD] -> out [2048, 50257]
    gemm_kernel<0><<<dim3(VPAD / GBN, MROWS / GBM), blk>>>(
        xn, embT, out, nullptr, nullptr, VDIM, CDIM, VPAD, VDIM);
}